// round 16
// baseline (speedup 1.0000x reference)
#include <cuda_runtime.h>
#include <cuda_fp16.h>
#include <math.h>
#include <stdint.h>

// Problem shape (fixed for this dataset instance)
constexpr int Bb = 4;
constexpr int Tt = 4096;
constexpr int Dd = 2048;
constexpr int BT = Bb * Tt;           // 16384 rows
constexpr float EPS = 1e-5f;

// Scan chunking
constexpr int NC = 64;
constexpr int CH = Tt / NC;           // 64
constexpr int D2 = Dd / 2;            // 1024 half2 channels

// GEMM tiling (mma.sync f16 m16n8k16 + ldmatrix): CTA 128x128, BK=64, 3 stages
constexpr int BM = 128;
constexpr int BN = 128;
constexpr int BK = 64;                // 4 x k16 per stage
constexpr int LDA_H = 72;             // A row: 64 data halves + 8 pad (144 B)
constexpr int LDB_H = 136;            // B row: 128 data halves + 8 pad (272 B)
constexpr int A_BYTES = BM * LDA_H * 2;               // 18432
constexpr int B_BYTES = BK * LDB_H * 2;               // 17408
constexpr int STG_BYTES = A_BYTES + B_BYTES;          // 35840
constexpr int GEMM_SMEM = 3 * STG_BYTES;              // 107520

// Scratch (device globals — no allocation allowed)
__device__ __half g_a   [(size_t)BT * Dd];     // sigmoid(f)
__device__ __half g_si  [(size_t)BT * Dd];     // silu(i)
__device__ __half g_gg  [(size_t)BT * Dd];     // silu(g)
__device__ __half g_o   [(size_t)BT * Dd];     // local (per-chunk) scan result
__device__ __half g_uh  [(size_t)BT * Dd];     // fp16 u (input to output GEMM)
__device__ __half g_xh  [(size_t)BT * Dd];     // fp16 x
__device__ __half g_wh  [(size_t)4 * Dd * Dd]; // fp16 weights, native [K][N]
__device__ float  g_cA  [(size_t)Bb * NC * Dd];
__device__ float  g_cH  [(size_t)Bb * NC * Dd];
__device__ float  g_cIn [(size_t)Bb * NC * Dd];

// ---------------------------------------------------------------------------
__device__ __forceinline__ void cp16(uint32_t dst, const void* src) {
    asm volatile("cp.async.cg.shared.global [%0], [%1], 16;\n" :: "r"(dst), "l"(src));
}

__device__ __forceinline__ void mma16816(float* d, const uint32_t* a, const uint32_t* b) {
    asm volatile(
        "mma.sync.aligned.m16n8k16.row.col.f32.f16.f16.f32 "
        "{%0,%1,%2,%3}, {%4,%5,%6,%7}, {%8,%9}, {%0,%1,%2,%3};"
        : "+f"(d[0]), "+f"(d[1]), "+f"(d[2]), "+f"(d[3])
        : "r"(a[0]), "r"(a[1]), "r"(a[2]), "r"(a[3]), "r"(b[0]), "r"(b[1]));
}

__device__ __forceinline__ void ldsm_x4(uint32_t& r0, uint32_t& r1,
                                        uint32_t& r2, uint32_t& r3, uint32_t addr) {
    asm volatile("ldmatrix.sync.aligned.m8n8.x4.shared.b16 {%0,%1,%2,%3}, [%4];"
                 : "=r"(r0), "=r"(r1), "=r"(r2), "=r"(r3) : "r"(addr));
}

__device__ __forceinline__ void ldsm_x4_t(uint32_t& r0, uint32_t& r1,
                                          uint32_t& r2, uint32_t& r3, uint32_t addr) {
    asm volatile("ldmatrix.sync.aligned.m8n8.x4.trans.shared.b16 {%0,%1,%2,%3}, [%4];"
                 : "=r"(r0), "=r"(r1), "=r"(r2), "=r"(r3) : "r"(addr));
}

__device__ __forceinline__ float sigm(float v) { return 1.0f / (1.0f + __expf(-v)); }

// ---------------------------------------------------------------------------
// float -> half, contiguous (x)
__global__ void f2h_kernel(const float* __restrict__ in,
                           __half* __restrict__ out, int n4)
{
    int i = blockIdx.x * blockDim.x + threadIdx.x;
    if (i < n4) {
        float4 v = reinterpret_cast<const float4*>(in)[i];
        __half2 h0 = __floats2half2_rn(v.x, v.y);
        __half2 h1 = __floats2half2_rn(v.z, v.w);
        uint2 p;
        p.x = *reinterpret_cast<uint32_t*>(&h0);
        p.y = *reinterpret_cast<uint32_t*>(&h1);
        reinterpret_cast<uint2*>(out)[i] = p;
    }
}

// Batched weight conversion: blockIdx.y selects the weight matrix
__global__ void f2h_w_kernel(const float* __restrict__ W0, const float* __restrict__ W1,
                             const float* __restrict__ W2, const float* __restrict__ W3,
                             __half* __restrict__ out)
{
    const size_t WSZ = (size_t)Dd * Dd;
    const float* in = (blockIdx.y == 0) ? W0 : (blockIdx.y == 1) ? W1
                    : (blockIdx.y == 2) ? W2 : W3;
    int i = blockIdx.x * blockDim.x + threadIdx.x;
    float4 v = reinterpret_cast<const float4*>(in)[i];
    __half2 h0 = __floats2half2_rn(v.x, v.y);
    __half2 h1 = __floats2half2_rn(v.z, v.w);
    uint2 p;
    p.x = *reinterpret_cast<uint32_t*>(&h0);
    p.y = *reinterpret_cast<uint32_t*>(&h1);
    reinterpret_cast<uint2*>(out + blockIdx.y * WSZ)[i] = p;
}

// ---------------------------------------------------------------------------
// C = act(A[M,K] * B[K,N]); A half [M,K], B half [K,N] native.
// MODE: 0 = identity (float C), 1 = sigmoid (half C), 2 = silu (half C).
// BK=64, 3-stage cp.async ring, prefetch-before-compute, ldmatrix, 2 CTAs/SM.
// ---------------------------------------------------------------------------
template <int MODE>
__global__ __launch_bounds__(256, 2)
void gemm_f16(const __half* __restrict__ A, const __half* __restrict__ Bh,
              void* __restrict__ Cout, int M, int N, int K)
{
    extern __shared__ char smem[];

    const int tid  = threadIdx.x;
    const int warp = tid >> 5;
    const int lane = tid & 31;
    const int wm   = warp >> 2;          // 0..1
    const int wn   = warp & 3;           // 0..3
    const int gid  = lane >> 2;          // 0..7
    const int tig  = lane & 3;           // 0..3
    const int m0   = blockIdx.y * BM;
    const int n0   = blockIdx.x * BN;

    const int lrow = ((lane >> 3) & 1) * 8 + (lane & 7);
    const int lcol = ((lane >> 4) & 1) * 8;

    float acc[4][4][4];
#pragma unroll
    for (int i = 0; i < 4; i++)
#pragma unroll
        for (int j = 0; j < 4; j++)
#pragma unroll
            for (int r = 0; r < 4; r++)
                acc[i][j][r] = 0.0f;

    const uint32_t smem_b = (uint32_t)__cvta_generic_to_shared(smem);

    auto load_stage = [&](int kt, int s) {
        const int k0 = kt * BK;
        const uint32_t sa = smem_b + s * STG_BYTES;
        const uint32_t sb = sa + A_BYTES;
        // A: 128 rows x 8 chunks of 16B -> 1024, 4/thread
#pragma unroll
        for (int i = 0; i < 4; i++) {
            int e = tid + i * 256;
            int r = e >> 3, c = e & 7;
            cp16(sa + r * (LDA_H * 2) + c * 16,
                 A + (size_t)(m0 + r) * K + k0 + c * 8);
        }
        // B: 64 rows x 16 chunks of 16B -> 1024, 4/thread
#pragma unroll
        for (int i = 0; i < 4; i++) {
            int e = tid + i * 256;
            int r = e >> 4, c = e & 15;
            cp16(sb + r * (LDB_H * 2) + c * 16,
                 Bh + (size_t)(k0 + r) * N + n0 + c * 8);
        }
        asm volatile("cp.async.commit_group;\n" ::: "memory");
    };

    const int KT = K / BK;               // 32
    load_stage(0, 0);
    load_stage(1, 1);

    for (int kt = 0; kt < KT; kt++) {
        const int s = kt % 3;
        if (kt < KT - 1)
            asm volatile("cp.async.wait_group 1;\n" ::: "memory");
        else
            asm volatile("cp.async.wait_group 0;\n" ::: "memory");
        __syncthreads();

        // Prefetch into the buffer freed at the previous iteration
        if (kt + 2 < KT)
            load_stage(kt + 2, (kt + 2) % 3);

        const uint32_t sa = smem_b + s * STG_BYTES;
        const uint32_t sb = sa + A_BYTES;

#pragma unroll
        for (int kk = 0; kk < 4; kk++) {             // four k16 steps
            uint32_t af[4][4];
            uint32_t bf[4][2];
#pragma unroll
            for (int im = 0; im < 4; im++) {
                uint32_t addr = sa +
                    ((wm * 64 + im * 16 + lrow) * LDA_H + kk * 16 + lcol) * 2;
                ldsm_x4(af[im][0], af[im][1], af[im][2], af[im][3], addr);
            }
#pragma unroll
            for (int p = 0; p < 2; p++) {
                uint32_t addr = sb +
                    ((kk * 16 + lrow) * LDB_H + wn * 32 + p * 16 + lcol) * 2;
                ldsm_x4_t(bf[2 * p][0], bf[2 * p][1],
                          bf[2 * p + 1][0], bf[2 * p + 1][1], addr);
            }
#pragma unroll
            for (int im = 0; im < 4; im++)
#pragma unroll
                for (int in = 0; in < 4; in++)
                    mma16816(acc[im][in], af[im], bf[in]);
        }
    }

    // Epilogue: fused activation; half stores for gate modes, float for MODE 0
#pragma unroll
    for (int im = 0; im < 4; im++) {
        int row0 = m0 + wm * 64 + im * 16 + gid;
#pragma unroll
        for (int in = 0; in < 4; in++) {
            int col = n0 + wn * 32 + in * 8 + 2 * tig;
#pragma unroll
            for (int h = 0; h < 2; h++) {
                size_t off = (size_t)(row0 + 8 * h) * N + col;
                float v0 = acc[im][in][2 * h], v1 = acc[im][in][2 * h + 1];
                if (MODE == 0) {
                    *reinterpret_cast<float2*>(
                        reinterpret_cast<float*>(Cout) + off) = make_float2(v0, v1);
                } else {
                    if (MODE == 1) { v0 = sigm(v0);  v1 = sigm(v1); }
                    else           { v0 *= sigm(v0); v1 *= sigm(v1); }
                    __half2 hv = __floats2half2_rn(v0, v1);
                    *reinterpret_cast<uint32_t*>(
                        reinterpret_cast<__half*>(Cout) + off) =
                        *reinterpret_cast<uint32_t*>(&hv);
                }
            }
        }
    }
}

// ---------------------------------------------------------------------------
// Scan pass 1: local scan per chunk (2 channels/thread via half2)
// ---------------------------------------------------------------------------
__global__ void scan_pass1(const __half2* __restrict__ aA,
                           const __half2* __restrict__ siA,
                           __half2* __restrict__ o,
                           float2* __restrict__ cA,
                           float2* __restrict__ cH)
{
    const int blocksPerBC = D2 / 256;            // 4
    int d  = (blockIdx.x % blocksPerBC) * 256 + threadIdx.x;   // 0..1023
    int bc = blockIdx.x / blocksPerBC;
    int b  = bc / NC;
    int c  = bc % NC;
    size_t base = ((size_t)b * Tt + (size_t)c * CH) * D2 + d;

    float2 h  = make_float2(0.0f, 0.0f);
    float2 pa = make_float2(1.0f, 1.0f);
#pragma unroll 4
    for (int t = 0; t < CH; t++) {
        size_t idx = base + (size_t)t * D2;
        float2 a  = __half22float2(aA[idx]);
        float2 si = __half22float2(siA[idx]);
        h.x = fmaf(a.x, h.x, si.x * (1.0f - a.x));
        h.y = fmaf(a.y, h.y, si.y * (1.0f - a.y));
        pa.x *= a.x; pa.y *= a.y;
        o[idx] = __floats2half2_rn(h.x, h.y);
    }
    cA[(size_t)bc * D2 + d] = pa;
    cH[(size_t)bc * D2 + d] = h;
}

// Pass 2: sequential scan over NC chunk carries (tiny)
__global__ void scan_pass2(const float2* __restrict__ cA,
                           const float2* __restrict__ cH,
                           float2* __restrict__ cIn)
{
    int ch = blockIdx.x * blockDim.x + threadIdx.x;  // 0..Bb*D2-1
    int b  = ch / D2;
    int d  = ch - b * D2;
    float2 H = make_float2(0.0f, 0.0f);
#pragma unroll
    for (int c = 0; c < NC; c++) {
        size_t idx = ((size_t)b * NC + c) * D2 + d;
        cIn[idx] = H;
        float2 av = cA[idx], hv = cH[idx];
        H.x = fmaf(av.x, H.x, hv.x);
        H.y = fmaf(av.y, H.y, hv.y);
    }
}

// ---------------------------------------------------------------------------
// Fused fixup + RMSNorm + gate: one block per (b, chunk), 1024 thr x 2 ch.
// ---------------------------------------------------------------------------
__global__ __launch_bounds__(1024)
void scan_norm_kernel(const __half2* __restrict__ aA,
                      const __half2* __restrict__ oL,
                      const float2* __restrict__ cIn,
                      const __half2* __restrict__ gsw,
                      const float* __restrict__ w,
                      __half* __restrict__ u)
{
    const int bc = blockIdx.x;                   // b*NC + c
    const int b  = bc / NC;
    const int c  = bc % NC;
    const int tid  = threadIdx.x;                // 0..1023
    const int lane = tid & 31;
    const int wrp  = tid >> 5;

    float2 pa = make_float2(0.0f, 0.0f);
    if (c > 0) pa = cIn[(size_t)bc * D2 + tid];
    const float2 wv = reinterpret_cast<const float2*>(w)[tid];

    __shared__ float sred[2][33];

    for (int t = 0; t < CH; t++) {
        size_t row = (size_t)b * Tt + (size_t)c * CH + t;
        size_t off = row * D2 + tid;
        float2 av = __half22float2(aA[off]);
        float2 ov = __half22float2(oL[off]);
        float2 gv = __half22float2(gsw[off]);
        pa.x *= av.x; pa.y *= av.y;
        float ox = ov.x + pa.x;
        float oy = ov.y + pa.y;

        float s = ox * ox + oy * oy;
#pragma unroll
        for (int k = 16; k > 0; k >>= 1)
            s += __shfl_xor_sync(0xffffffffu, s, k);
        const int buf = t & 1;
        if (lane == 0) sred[buf][wrp] = s;
        __syncthreads();
        if (tid < 32) {
            float v = sred[buf][tid];
#pragma unroll
            for (int k = 16; k > 0; k >>= 1)
                v += __shfl_xor_sync(0xffffffffu, v, k);
            if (tid == 0) sred[buf][32] = v;
        }
        __syncthreads();
        float r = rsqrtf(sred[buf][32] * (1.0f / Dd) + EPS);

        __half2 h = __floats2half2_rn(ox * r * wv.x * gv.x,
                                      oy * r * wv.y * gv.y);
        reinterpret_cast<uint32_t*>(u)[off] = *reinterpret_cast<uint32_t*>(&h);
    }
}

// ---------------------------------------------------------------------------
extern "C" void kernel_launch(void* const* d_in, const int* in_sizes, int n_in,
                              void* d_out, int out_size)
{
    const float* x  = (const float*)d_in[0];
    const float* Wi = (const float*)d_in[1];
    const float* Wf = (const float*)d_in[2];
    const float* Wg = (const float*)d_in[3];
    const float* Wo = (const float*)d_in[4];
    const float* gw = (const float*)d_in[5];
    float* out = (float*)d_out;

    __half *aA, *siA, *gg, *o, *uh, *xh, *wh;
    float *cA, *cH, *cIn;
    cudaGetSymbolAddress((void**)&aA,  g_a);
    cudaGetSymbolAddress((void**)&siA, g_si);
    cudaGetSymbolAddress((void**)&gg,  g_gg);
    cudaGetSymbolAddress((void**)&o,   g_o);
    cudaGetSymbolAddress((void**)&uh,  g_uh);
    cudaGetSymbolAddress((void**)&xh,  g_xh);
    cudaGetSymbolAddress((void**)&wh,  g_wh);
    cudaGetSymbolAddress((void**)&cA,  g_cA);
    cudaGetSymbolAddress((void**)&cH,  g_cH);
    cudaGetSymbolAddress((void**)&cIn, g_cIn);

    cudaFuncSetAttribute(gemm_f16<0>,
                         cudaFuncAttributeMaxDynamicSharedMemorySize, GEMM_SMEM);
    cudaFuncSetAttribute(gemm_f16<1>,
                         cudaFuncAttributeMaxDynamicSharedMemorySize, GEMM_SMEM);
    cudaFuncSetAttribute(gemm_f16<2>,
                         cudaFuncAttributeMaxDynamicSharedMemorySize, GEMM_SMEM);

    const size_t WSZ = (size_t)Dd * Dd;

    // Prep: x -> half; 4 weights in one batched launch
    {
        int n4x = (int)((size_t)BT * Dd / 4);
        f2h_kernel<<<n4x / 256, 256>>>(x, xh, n4x);
        dim3 wg((unsigned)(WSZ / 4 / 256), 4);
        f2h_w_kernel<<<wg, 256>>>(Wi, Wf, Wg, Wo, wh);
    }

    dim3 ggrid(Dd / BN, BT / BM);   // (16, 128)
    dim3 gblk(256);

    // i: silu(i); f: sigmoid(f); g: silu(g) — all fp16 outputs
    gemm_f16<2><<<ggrid, gblk, GEMM_SMEM>>>(xh, wh + 0 * WSZ, siA, BT, Dd, Dd);
    gemm_f16<1><<<ggrid, gblk, GEMM_SMEM>>>(xh, wh + 1 * WSZ, aA,  BT, Dd, Dd);
    gemm_f16<2><<<ggrid, gblk, GEMM_SMEM>>>(xh, wh + 2 * WSZ, gg,  BT, Dd, Dd);

    const int scanBlocks = Bb * NC * (D2 / 256);   // 1024
    scan_pass1<<<scanBlocks, 256>>>(
        reinterpret_cast<const __half2*>(aA),
        reinterpret_cast<const __half2*>(siA),
        reinterpret_cast<__half2*>(o),
        reinterpret_cast<float2*>(cA),
        reinterpret_cast<float2*>(cH));
    scan_pass2<<<(Bb * D2) / 256, 256>>>(
        reinterpret_cast<const float2*>(cA),
        reinterpret_cast<const float2*>(cH),
        reinterpret_cast<float2*>(cIn));

    scan_norm_kernel<<<Bb * NC, 1024>>>(
        reinterpret_cast<const __half2*>(aA),
        reinterpret_cast<const __half2*>(o),
        reinterpret_cast<const float2*>(cIn),
        reinterpret_cast<const __half2*>(gg),
        gw, uh);

    // Output GEMM (identity epilogue, float output)
    gemm_f16<0><<<ggrid, gblk, GEMM_SMEM>>>(uh, wh + 3 * WSZ, out, BT, Dd, Dd);
}